// round 4
// baseline (speedup 1.0000x reference)
#include <cuda_runtime.h>

#define TT   512
#define BB   2048
#define DD   8
#define HH   4
#define NTAG 16

// scratch: h sequence (T, B, 4) fp32 = 16.8 MB
__device__ float g_h[(size_t)TT * BB * HH];

__device__ __forceinline__ float rcp_ap(float x)  { float r; asm("rcp.approx.f32 %0, %1;"  : "=f"(r) : "f"(x)); return r; }
__device__ __forceinline__ float ex2_ap(float x)  { float r; asm("ex2.approx.f32 %0, %1;"  : "=f"(r) : "f"(x)); return r; }
__device__ __forceinline__ float lg2_ap(float x)  { float r; asm("lg2.approx.f32 %0, %1;"  : "=f"(r) : "f"(x)); return r; }
__device__ __forceinline__ float cos_ap(float x)  { float r; asm("cos.approx.f32 %0, %1;"  : "=f"(r) : "f"(x)); return r; }

#define LOG2E 1.4426950408889634f

// ---------------------------------------------------------------------------
// Kernel A: the LSTM recurrence. 4 lanes per batch chain (one per gate g).
// Lane g computes pre[g][0..3], c=cos, e-products, gate nonlinearity; the four
// gate vectors are exchanged with shfl (width=4); cx/h are replicated per lane.
//
// Gate math (exact formulas, ~1e-6 error):
//   sigmoid(e) = rcp(ex2(-e*log2e)+1)
//   tanh(e)    = fma(-2, rcp(ex2(2e*log2e)+1), 1)
// unified as  v = fma(A, rcp(ex2(m*e)+1), B), per-lane (m,A,B).
// ---------------------------------------------------------------------------
__global__ void __launch_bounds__(32, 1)
recur_kernel(const float* __restrict__ x,
             const float* __restrict__ w_gates,
             const float* __restrict__ b_gates,
             const float* __restrict__ rx_theta)
{
    const int tid = blockIdx.x * 32 + threadIdx.x;   // 0..8191
    const int b   = tid >> 2;                        // batch chain 0..2047
    const int g   = tid & 3;                         // gate (f,i,g,o)

    // per-lane weights: w_gates layout (4,4,12): [g*48 + k*12 + d]
    float wx[4][8], wh[4][4], th[4];
#pragma unroll
    for (int k = 0; k < 4; k++) {
#pragma unroll
        for (int d = 0; d < 8; d++) wx[k][d] = w_gates[g*48 + k*12 + d];
#pragma unroll
        for (int j = 0; j < 4; j++) wh[k][j] = w_gates[g*48 + k*12 + 8 + j];
        th[k] = b_gates[g*4 + k] + rx_theta[g*4 + k];
    }
    // lane 2 is the tanh gate; lanes 0,1,3 are sigmoid gates
    const float gm = (g == 2) ?  2.0f * LOG2E : -LOG2E;
    const float gA = (g == 2) ? -2.0f         :  1.0f;
    const float gB = (g == 2) ?  1.0f         :  0.0f;

    float h0 = 0.f, h1 = 0.f, h2 = 0.f, h3 = 0.f;
    float cx[4] = {0.f, 0.f, 0.f, 0.f};

    const float4* xp = (const float4*)x;             // (t*BB + b)*2 indexing
    float4 xa[4], xb[4];                             // 4-deep prefetch ring
#pragma unroll
    for (int p = 0; p < 4; p++) {
        size_t i = ((size_t)p * BB + b) * 2;
        xa[p] = xp[i]; xb[p] = xp[i + 1];
    }

    // x-part of pre for t=0 (computed one step ahead of use); consumes slot 0
    float xacc[4];
    {
        float xv[8] = {xa[0].x, xa[0].y, xa[0].z, xa[0].w,
                       xb[0].x, xb[0].y, xb[0].z, xb[0].w};
#pragma unroll
        for (int k = 0; k < 4; k++) {
            float q = fmaf(xv[0], wx[k][0], th[k]);
            q = fmaf(xv[1], wx[k][1], q); q = fmaf(xv[2], wx[k][2], q);
            q = fmaf(xv[3], wx[k][3], q); q = fmaf(xv[4], wx[k][4], q);
            q = fmaf(xv[5], wx[k][5], q); q = fmaf(xv[6], wx[k][6], q);
            xacc[k] = fmaf(xv[7], wx[k][7], q);
        }
    }
    // BUGFIX (R3): slot 0 is next used at t=3 to build xacc(t=4) -> must hold x[4].
    {
        size_t i4 = ((size_t)4 * BB + b) * 2;
        xa[0] = xp[i4]; xb[0] = xp[i4 + 1];
    }

    float4* hout = (float4*)g_h;

#pragma unroll 4
    for (int t = 0; t < TT; t++) {
        // ---- pre = xacc + Wh·h ; c = cos(pre) (h-critical path) ----
        float c0, c1, c2, c3;
        {
            float s0, s1;
            s0 = fmaf(h1, wh[0][1], fmaf(h0, wh[0][0], xacc[0]));
            s1 = fmaf(h3, wh[0][3], h2 * wh[0][2]);
            c0 = cos_ap(s0 + s1);
            s0 = fmaf(h1, wh[1][1], fmaf(h0, wh[1][0], xacc[1]));
            s1 = fmaf(h3, wh[1][3], h2 * wh[1][2]);
            c1 = cos_ap(s0 + s1);
            s0 = fmaf(h1, wh[2][1], fmaf(h0, wh[2][0], xacc[2]));
            s1 = fmaf(h3, wh[2][3], h2 * wh[2][2]);
            c2 = cos_ap(s0 + s1);
            s0 = fmaf(h1, wh[3][1], fmaf(h0, wh[3][0], xacc[3]));
            s1 = fmaf(h3, wh[3][3], h2 * wh[3][2]);
            c3 = cos_ap(s0 + s1);
        }

        // ---- off-path: compute next step's x-part, then refill the ring ----
        {
            int slot = (t + 1) & 3;
            float xv[8] = {xa[slot].x, xa[slot].y, xa[slot].z, xa[slot].w,
                           xb[slot].x, xb[slot].y, xb[slot].z, xb[slot].w};
#pragma unroll
            for (int k = 0; k < 4; k++) {
                float q = fmaf(xv[0], wx[k][0], th[k]);
                q = fmaf(xv[1], wx[k][1], q); q = fmaf(xv[2], wx[k][2], q);
                q = fmaf(xv[3], wx[k][3], q); q = fmaf(xv[4], wx[k][4], q);
                q = fmaf(xv[5], wx[k][5], q); q = fmaf(xv[6], wx[k][6], q);
                xacc[k] = fmaf(xv[7], wx[k][7], q);
            }
            int tp = t + 5; if (tp > TT - 1) tp = TT - 1;
            size_t i = ((size_t)tp * BB + b) * 2;
            xa[slot] = xp[i]; xb[slot] = xp[i + 1];
        }

        // ---- expvals: e0=c1c2c3, e1=c0c1, e2=e1c2, e3=e1c2c3 ----
        float t23 = c2 * c3;
        float e1  = c0 * c1;
        float e0  = c1 * t23;
        float e2  = e1 * c2;
        float e3  = e1 * t23;

        // ---- gate nonlinearity on own lane: v = fma(A, rcp(ex2(m*e)+1), B) ----
        float r0 = rcp_ap(ex2_ap(gm * e0) + 1.0f);
        float r1 = rcp_ap(ex2_ap(gm * e1) + 1.0f);
        float r2 = rcp_ap(ex2_ap(gm * e2) + 1.0f);
        float r3 = rcp_ap(ex2_ap(gm * e3) + 1.0f);
        float v0 = fmaf(gA, r0, gB);
        float v1 = fmaf(gA, r1, gB);
        float v2 = fmaf(gA, r2, gB);
        float v3 = fmaf(gA, r3, gB);

        // ---- gather all 4 gate vectors into every lane (16 independent shfl) ----
        float tg0[4], tg1[4], tg2[4], tg3[4];
#pragma unroll
        for (int s = 0; s < 4; s++) {
            tg0[s] = __shfl_sync(0xffffffffu, v0, s, 4);
            tg1[s] = __shfl_sync(0xffffffffu, v1, s, 4);
            tg2[s] = __shfl_sync(0xffffffffu, v2, s, 4);
            tg3[s] = __shfl_sync(0xffffffffu, v3, s, 4);
        }
        // tgK[s] = gate-s value for wire K. s: 0=f, 1=i, 2=g, 3=o.

        // ---- combine (replicated in all lanes) ----
        float hn[4];
#pragma unroll
        for (int k = 0; k < 4; k++) {
            float F = (k==0)?tg0[0]:(k==1)?tg1[0]:(k==2)?tg2[0]:tg3[0];
            float I = (k==0)?tg0[1]:(k==1)?tg1[1]:(k==2)?tg2[1]:tg3[1];
            float G = (k==0)?tg0[2]:(k==1)?tg1[2]:(k==2)?tg2[2]:tg3[2];
            float O = (k==0)?tg0[3]:(k==1)?tg1[3]:(k==2)?tg2[3]:tg3[3];
            float nc = fmaf(F, cx[k], I * G);
            cx[k] = nc;
            // tanh(cx) = 1 - 2/(exp(2cx)+1)
            float E  = ex2_ap(nc * (2.0f * LOG2E));
            float r  = rcp_ap(E + 1.0f);
            float tc = fmaf(-2.0f, r, 1.0f);
            hn[k] = O * tc;                              // o * tanh(cx)
        }
        h0 = hn[0]; h1 = hn[1]; h2 = hn[2]; h3 = hn[3];

        if (g == 0)
            hout[(size_t)t * BB + b] = make_float4(h0, h1, h2, h3);
    }
}

// ---------------------------------------------------------------------------
// Kernel B: logits + log_softmax, embarrassingly parallel, memory-bound.
// ---------------------------------------------------------------------------
__global__ void __launch_bounds__(256)
out_kernel(const float* __restrict__ w_tag,
           const float* __restrict__ b_tag,
           float* __restrict__ out)
{
    float w[NTAG][4], bt[NTAG];
#pragma unroll
    for (int j = 0; j < NTAG; j++) {
#pragma unroll
        for (int k = 0; k < 4; k++) w[j][k] = w_tag[j*4 + k];
        bt[j] = b_tag[j];
    }

    const int NITEM = TT * BB;                 // 1,048,576 rows
    const int NTH   = gridDim.x * blockDim.x;  // 131,072 threads
    int tid = blockIdx.x * blockDim.x + threadIdx.x;

    const float4* hv4 = (const float4*)g_h;
    float4* o4 = (float4*)out;

    for (int it = tid; it < NITEM; it += NTH) {
        float4 hv = hv4[it];
        float lg[NTAG];
#pragma unroll
        for (int j = 0; j < NTAG; j++) {
            lg[j] = fmaf(w[j][3], hv.w,
                    fmaf(w[j][2], hv.z,
                    fmaf(w[j][1], hv.y,
                    fmaf(w[j][0], hv.x, bt[j]))));
        }
        float m = lg[0];
#pragma unroll
        for (int j = 1; j < NTAG; j++) m = fmaxf(m, lg[j]);
        float s = 0.f;
#pragma unroll
        for (int j = 0; j < NTAG; j++)
            s += ex2_ap((lg[j] - m) * LOG2E);
        float ls = fmaf(lg2_ap(s), 0.6931471805599453f, m);
#pragma unroll
        for (int j = 0; j < NTAG; j += 4) {
            o4[(size_t)it * 4 + (j >> 2)] =
                make_float4(lg[j] - ls, lg[j+1] - ls, lg[j+2] - ls, lg[j+3] - ls);
        }
    }
}

extern "C" void kernel_launch(void* const* d_in, const int* in_sizes, int n_in,
                              void* d_out, int out_size)
{
    const float* x        = (const float*)d_in[0];
    const float* w_gates  = (const float*)d_in[1];
    const float* b_gates  = (const float*)d_in[2];
    const float* rx_theta = (const float*)d_in[3];
    const float* w_tag    = (const float*)d_in[4];
    const float* b_tag    = (const float*)d_in[5];

    recur_kernel<<<256, 32>>>(x, w_gates, b_gates, rx_theta);   // 8192 threads
    out_kernel<<<512, 256>>>(w_tag, b_tag, (float*)d_out);      // 131072 threads
}